// round 11
// baseline (speedup 1.0000x reference)
#include <cuda_runtime.h>

#define B_ 128
#define L_ 4096
#define H_ 64
#define V_ 64
#define HALF_ 32
#define C1 0.05f
#define LN_EPS 1e-5f
#define L_PAD (L_ + 8)
#define MID_ 2049
#define N0_ 2049
#define N1_ 2046
#define NB_ 2046
#define NT_ 320

typedef unsigned long long ull;

// Token-indexed tables (V=64): g_hs/g_he pre-scaled by (1-ALPHA)=C1.
__device__ float g_hs[V_ * HALF_];
__device__ float g_he[V_ * HALF_];
__device__ float g_ks[V_ * HALF_];
__device__ float g_ke[V_ * HALF_];

// ---------------- packed f32x2 helpers ----------------
__device__ __forceinline__ ull fma2(ull a, ull b, ull c) {
    ull d; asm("fma.rn.f32x2 %0,%1,%2,%3;" : "=l"(d) : "l"(a), "l"(b), "l"(c)); return d;
}
__device__ __forceinline__ ull mul2(ull a, ull b) {
    ull d; asm("mul.rn.f32x2 %0,%1,%2;" : "=l"(d) : "l"(a), "l"(b)); return d;
}
__device__ __forceinline__ ull add2(ull a, ull b) {
    ull d; asm("add.rn.f32x2 %0,%1,%2;" : "=l"(d) : "l"(a), "l"(b)); return d;
}
__device__ __forceinline__ ull pack2(float x) {
    ull d; asm("mov.b64 %0,{%1,%1};" : "=l"(d) : "f"(x)); return d;
}
__device__ __forceinline__ float2 unpack2(ull v) {
    float2 r; asm("mov.b64 {%0,%1},%2;" : "=f"(r.x), "=f"(r.y) : "l"(v)); return r;
}
__device__ __forceinline__ float reduce2(ull a0, ull a1) {
    ull s = add2(a0, a1);
    float2 f = unpack2(s);
    float h = f.x + f.y;
    return h + __shfl_xor_sync(0xffffffffu, h, 1);
}

// load 16 floats (8 f32x2) of token's key row starting at col0
#define LOADK(DST, TOK) { \
    const ulonglong2* p_ = (const ulonglong2*)(kT + ((TOK) << 5) + col0); \
    ulonglong2 x_ = p_[0], y_ = p_[1]; \
    DST[0] = x_.x; DST[1] = x_.y; DST[2] = y_.x; DST[3] = y_.y; \
    const ulonglong2* q_ = (const ulonglong2*)(kT + ((TOK) << 5) + col0 + 8); \
    ulonglong2 z_ = q_[0], u_ = q_[1]; \
    DST[4] = z_.x; DST[5] = z_.y; DST[6] = u_.x; DST[7] = u_.y; }

// ---------------------------------------------------------------------------
// Kernel 1: per-token precompute. grid=64 (token), block=128.
// ---------------------------------------------------------------------------
__global__ void build_tables(const float* __restrict__ embed,
                             const float* __restrict__ W1, const float* __restrict__ b1,
                             const float* __restrict__ W2, const float* __restrict__ b2,
                             const float* __restrict__ gamma, const float* __restrict__ beta,
                             const float* __restrict__ Ws, const float* __restrict__ bs,
                             const float* __restrict__ We, const float* __restrict__ be)
{
    __shared__ float s_e[H_];
    __shared__ float s_a[2 * H_];
    __shared__ float s_x[H_];
    __shared__ float s_h[H_];
    __shared__ float s_mu, s_rstd;

    int tok = blockIdx.x;
    int tid = threadIdx.x;

    if (tid < H_) s_e[tid] = embed[tok * H_ + tid];
    __syncthreads();

    {
        float acc = b1[tid];
        #pragma unroll 32
        for (int h = 0; h < H_; ++h) acc = fmaf(s_e[h], __ldg(W1 + h * 2 * H_ + tid), acc);
        s_a[tid] = fmaxf(acc, 0.0f);
    }
    __syncthreads();

    if (tid < H_) {
        float acc = b2[tid];
        #pragma unroll 32
        for (int k = 0; k < 2 * H_; ++k) acc = fmaf(s_a[k], __ldg(W2 + k * H_ + tid), acc);
        s_x[tid] = s_e[tid] + acc;
    }
    __syncthreads();

    if (tid < 32) {
        float v = s_x[tid] + s_x[tid + 32];
        #pragma unroll
        for (int m = 16; m > 0; m >>= 1) v += __shfl_xor_sync(0xffffffffu, v, m);
        const float mu = v * (1.0f / H_);
        float d0 = s_x[tid] - mu, d1 = s_x[tid + 32] - mu;
        float vv = fmaf(d0, d0, d1 * d1);
        #pragma unroll
        for (int m = 16; m > 0; m >>= 1) vv += __shfl_xor_sync(0xffffffffu, vv, m);
        if (tid == 0) {
            s_mu = mu;
            s_rstd = rsqrtf(vv * (1.0f / H_) + LN_EPS);
        }
    }
    __syncthreads();

    if (tid < H_) s_h[tid] = (s_x[tid] - s_mu) * s_rstd * gamma[tid] + beta[tid];
    __syncthreads();

    int wid = tid >> 5, lane = tid & 31;
    if (wid == 0) {
        float acc = bs[lane];
        #pragma unroll 32
        for (int j = 0; j < H_; ++j) acc = fmaf(s_h[j], __ldg(Ws + j * HALF_ + lane), acc);
        float ss = acc * acc;
        #pragma unroll
        for (int m = 16; m > 0; m >>= 1) ss += __shfl_xor_sync(0xffffffffu, ss, m);
        float n = fmaxf(sqrtf(ss), 1e-12f);
        g_hs[tok * HALF_ + lane] = C1 * acc;
        g_ks[tok * HALF_ + lane] = acc / n;
    } else if (wid == 1) {
        float acc = be[lane];
        #pragma unroll 32
        for (int j = 0; j < H_; ++j) acc = fmaf(s_h[j], __ldg(We + j * HALF_ + lane), acc);
        float ss = acc * acc;
        #pragma unroll
        for (int m = 16; m > 0; m >>= 1) ss += __shfl_xor_sync(0xffffffffu, ss, m);
        float n = fmaxf(sqrtf(ss), 1e-12f);
        g_he[tok * HALF_ + lane] = C1 * acc;
        g_ke[tok * HALF_ + lane] = acc / n;
    }
}

// ---------------------------------------------------------------------------
// Forward chunk scan (R6 body): N steps over toks[0..N-1] starting from M=0.
// On exit: m = M^(N); (r_dm1, r_g, r_full) give the deferred dot of
// k_{toks[N]} on M: full = fullred + dm1*g = M^(N) . k_{toks[N]}.
// Requires N % 3 == 0. Reads toks up to toks[N+1].
// ---------------------------------------------------------------------------
#define STEPX(T, KU, KL) { \
    const int tok_n2 = toks[(T) + 2]; \
    const float g_nxt = gT[(tok_cur << 6) + tok_nxt]; \
    const float h_nxt = hT[(tok_nxt << 5) + row]; \
    const float hsc_nxt = sc_nxt * h_nxt; \
    const float csc_nxt = -C1 * sc_nxt; \
    LOADK(KL, tok_n2); \
    const float ps = fmaf(dm1, g_cur, fullred); \
    const float dn = fmaf(csc_cur, ps, hsc_cur); \
    const ull dn2 = pack2(dn); \
    { ull s01_ = add2(acc0, acc1); \
      float2 lh_ = unpack2(s01_); \
      float hs_ = lh_.x + lh_.y; \
      fullred = hs_ + __shfl_xor_sync(0xffffffffu, hs_, 1); } \
    m[0] = fma2(dn2, KU[0], m[0]); m[1] = fma2(dn2, KU[1], m[1]); \
    m[2] = fma2(dn2, KU[2], m[2]); m[3] = fma2(dn2, KU[3], m[3]); \
    m[4] = fma2(dn2, KU[4], m[4]); m[5] = fma2(dn2, KU[5], m[5]); \
    m[6] = fma2(dn2, KU[6], m[6]); m[7] = fma2(dn2, KU[7], m[7]); \
    acc0 = mul2(m[0], KL[0]); acc1 = mul2(m[1], KL[1]); \
    acc0 = fma2(m[2], KL[2], acc0); acc1 = fma2(m[3], KL[3], acc1); \
    acc0 = fma2(m[4], KL[4], acc0); acc1 = fma2(m[5], KL[5], acc1); \
    acc0 = fma2(m[6], KL[6], acc0); acc1 = fma2(m[7], KL[7], acc1); \
    dm1 = dn; g_cur = g_nxt; hsc_cur = hsc_nxt; csc_cur = csc_nxt; \
    tok_cur = tok_nxt; tok_nxt = tok_n2; \
    sc_nxt += scStep; }

template<int N>
__device__ __forceinline__ void scan_chunk(
    const float* __restrict__ kT, const float* __restrict__ hT,
    const float* __restrict__ gT, const int* __restrict__ toks,
    const int row, const int col0,
    const float scBase, float scStep,
    ull m[8], float& r_dm1, float& r_g, float& r_full)
{
    ull kb0[8], kb1[8], kb2[8];
    ull acc0, acc1;

    const int v0 = toks[0];
    int tok_cur = toks[1];
    int tok_nxt = toks[2];

    const float sc1 = scBase + scStep;

    // step 0 (M = 0 -> ps = 0)
    float dm1 = scBase * hT[(v0 << 5) + row];
    LOADK(kb0, v0);
    {
        const ull d2_ = pack2(dm1);
        #pragma unroll
        for (int j = 0; j < 8; ++j) m[j] = mul2(d2_, kb0[j]);
    }
    LOADK(kb1, tok_cur);
    LOADK(kb2, tok_nxt);
    acc0 = mul2(m[0], kb2[0]); acc1 = mul2(m[1], kb2[1]);
    acc0 = fma2(m[2], kb2[2], acc0); acc1 = fma2(m[3], kb2[3], acc1);
    acc0 = fma2(m[4], kb2[4], acc0); acc1 = fma2(m[5], kb2[5], acc1);
    acc0 = fma2(m[6], kb2[6], acc0); acc1 = fma2(m[7], kb2[7], acc1);

    float fullred = 0.0f;
    float g_cur = gT[(v0 << 6) + tok_cur];
    float hsc_cur = sc1 * hT[(tok_cur << 5) + row];
    float csc_cur = -C1 * sc1;
    float sc_nxt = scBase + 2.0f * scStep;

    for (int s = 1; s <= N - 5; s += 3) {
        STEPX(s,     kb1, kb0);
        STEPX(s + 1, kb2, kb1);
        STEPX(s + 2, kb0, kb2);
    }
    STEPX(N - 2, kb1, kb0);
    STEPX(N - 1, kb2, kb1);

    r_dm1 = dm1; r_g = g_cur; r_full = fullred;
}

// ---------------------------------------------------------------------------
// Backward vector pass over chunk1: p = (A_MID ... A_{L-2}) q,
// A_t = I - c_t k_t k_t^T. u split across lane parity (16 cols each, f32x2).
// Deferred-by-1 via Gram: dot_j = raw_j - d_{j-1}*G(tok_j, tok_{j-1}).
// ---------------------------------------------------------------------------
__device__ __forceinline__ void backward_pass(
    const float* __restrict__ kT, const float* __restrict__ gT,
    const int* __restrict__ sseq, const int col0, const int lane,
    const float cBase, const float cStep, float* __restrict__ p_out)
{
    ull u[8], ka[8], kb[8];
    const int tokq = sseq[L_ - 1];
    LOADK(u, tokq);                       // u = q

    int tok_c = sseq[L_ - 2];             // token at t_0 = L-2
    int tok_p = tok_c;
    LOADK(ka, tok_c);

    float raw;
    {
        ull a0 = mul2(ka[0], u[0]), a1 = mul2(ka[1], u[1]);
        a0 = fma2(ka[2], u[2], a0); a1 = fma2(ka[3], u[3], a1);
        a0 = fma2(ka[4], u[4], a0); a1 = fma2(ka[5], u[5], a1);
        a0 = fma2(ka[6], u[6], a0); a1 = fma2(ka[7], u[7], a1);
        raw = reduce2(a0, a1);            // raw_0 = k_0 . u^(0) (exact)
    }
    float dprev = 0.0f;
    float c = cBase;

    #define BITER(KC, KN, J) { \
        const int tok_n = sseq[L_ - 3 - (J)]; \
        LOADK(KN, tok_n); \
        /* partials for raw_{j+1} on u^(j) (pre-update) */ \
        ull a0_ = mul2(KN[0], u[0]), a1_ = mul2(KN[1], u[1]); \
        a0_ = fma2(KN[2], u[2], a0_); a1_ = fma2(KN[3], u[3], a1_); \
        a0_ = fma2(KN[4], u[4], a0_); a1_ = fma2(KN[5], u[5], a1_); \
        a0_ = fma2(KN[6], u[6], a0_); a1_ = fma2(KN[7], u[7], a1_); \
        const float g_ = gT[(tok_c << 6) + tok_p]; \
        const float d_ = fmaf(-dprev, c * g_, c * raw); \
        const ull nd2_ = pack2(-d_); \
        u[0] = fma2(nd2_, KC[0], u[0]); u[1] = fma2(nd2_, KC[1], u[1]); \
        u[2] = fma2(nd2_, KC[2], u[2]); u[3] = fma2(nd2_, KC[3], u[3]); \
        u[4] = fma2(nd2_, KC[4], u[4]); u[5] = fma2(nd2_, KC[5], u[5]); \
        u[6] = fma2(nd2_, KC[6], u[6]); u[7] = fma2(nd2_, KC[7], u[7]); \
        raw = reduce2(a0_, a1_); \
        dprev = d_; tok_p = tok_c; tok_c = tok_n; c += cStep; }

    for (int j = 0; j < NB_; j += 2) {
        BITER(ka, kb, j);
        BITER(kb, ka, j + 1);
    }
    #undef BITER

    if (lane < 2) {
        ull* po = (ull*)(p_out + col0);
        #pragma unroll
        for (int i = 0; i < 8; ++i) po[i] = u[i];
    }
}

// ---------------------------------------------------------------------------
// Kernel 2: time-split delta-rule scan. grid = B, block = 320 (10 warps).
// w0-3: chunk0 scans (s lo/hi, e lo/hi); w4-7: chunk1 scans (+ q readout);
// w8/w9: backward vector pass (s/e). r = M_c0 . p + Q . q.
// ---------------------------------------------------------------------------
__global__ __launch_bounds__(NT_, 1)
void scan_kernel(const int* __restrict__ seq,
                 const float* __restrict__ Wrp, const float* __restrict__ brp,
                 const float* __restrict__ Wout, const float* __restrict__ bout,
                 float* __restrict__ out)
{
    extern __shared__ float sm[];
    float* s_ks = sm;                          // 2048
    float* s_ke = sm + 2048;                   // 2048
    float* s_hs = sm + 4096;                   // 2048
    float* s_he = sm + 6144;                   // 2048
    float* s_Gs = sm + 8192;                   // 4096
    float* s_Ge = sm + 12288;                  // 4096
    int*   s_seq = (int*)(sm + 16384);         // L_PAD ints
    float* s_p   = sm + 16384 + L_PAD;         // 64 (p_s | p_e)
    float* s_r1  = s_p + 64;                   // 64
    float* s_r2  = s_r1 + 64;                  // 64
    float* s_tmp = s_r2 + 64;                  // 64

    const int b = blockIdx.x;
    const int tid = threadIdx.x;
    const int wid = tid >> 5;
    const int lane = tid & 31;

    // stage sequence + tables
    {
        const int* seqb = seq + b * L_;
        for (int k = tid; k < L_; k += NT_) s_seq[k] = seqb[k];
        if (tid < 8) s_seq[L_ + tid] = 0;
    }
    for (int k = tid; k < V_ * HALF_; k += NT_) {
        s_ks[k] = g_ks[k];
        s_ke[k] = g_ke[k];
        s_hs[k] = g_hs[k];
        s_he[k] = g_he[k];
    }
    __syncthreads();

    // Gram tables in-CTA
    for (int idx = tid; idx < V_ * V_; idx += NT_) {
        const int a = idx >> 6, c = idx & 63;
        float ss = 0.f, se = 0.f;
        #pragma unroll
        for (int j = 0; j < HALF_; ++j) {
            ss = fmaf(s_ks[a * HALF_ + j], s_ks[c * HALF_ + j], ss);
            se = fmaf(s_ke[a * HALF_ + j], s_ke[c * HALF_ + j], se);
        }
        s_Gs[idx] = ss;
        s_Ge[idx] = se;
    }
    __syncthreads();

    const float invL = 1.0f / (float)L_;
    const int col0 = (lane & 1) << 4;

    ull m[8];
    bool c0_is_e = false;
    int row = 0;

    if (wid < 8) {
        const int chunk = (wid >> 2) & 1;
        const bool is_e = ((wid >> 1) & 1) != 0;
        const int hilo = wid & 1;
        row = (hilo << 4) | (lane >> 1);
        c0_is_e = is_e;

        const float* kT = is_e ? s_ke : s_ks;
        const float* hT = is_e ? s_he : s_hs;
        const float* gT = is_e ? s_Ge : s_Gs;
        const float scStep = is_e ? invL : 0.0f;

        if (chunk == 0) {
            const float scBase = is_e ? invL : 1.0f;
            float rdm1, rg, rfull;
            scan_chunk<N0_>(kT, hT, gT, s_seq, row, col0, scBase, scStep,
                            m, rdm1, rg, rfull);
            // m = M^(MID) kept for epilogue
        } else {
            const float scBase = is_e ? (float)(MID_ + 1) * invL : 1.0f;
            float rdm1, rg, rfull;
            scan_chunk<N1_>(kT, hT, gT, s_seq + MID_, row, col0, scBase, scStep,
                            m, rdm1, rg, rfull);
            const float r2 = fmaf(rdm1, rg, rfull);   // Q . q
            if ((lane & 1) == 0) s_r2[(is_e ? HALF_ : 0) + row] = r2;
        }
    } else {
        const bool is_e = (wid == 9);
        const float* kT = is_e ? s_ke : s_ks;
        const float* gT = is_e ? s_Ge : s_Gs;
        const float cBase = is_e ? C1 * (float)(L_ - 1) * invL : C1;
        const float cStep = is_e ? -C1 * invL : 0.0f;
        backward_pass(kT, gT, s_seq, col0, lane, cBase, cStep,
                      s_p + (is_e ? HALF_ : 0));
    }
    __syncthreads();

    // r1 = M_c0 . p  (chunk0 warps)
    if (wid < 4) {
        const float* pv = s_p + (c0_is_e ? HALF_ : 0);
        const ull* pp = (const ull*)(pv + col0);
        ull a0 = mul2(m[0], pp[0]), a1 = mul2(m[1], pp[1]);
        a0 = fma2(m[2], pp[2], a0); a1 = fma2(m[3], pp[3], a1);
        a0 = fma2(m[4], pp[4], a0); a1 = fma2(m[5], pp[5], a1);
        a0 = fma2(m[6], pp[6], a0); a1 = fma2(m[7], pp[7], a1);
        const float r1 = reduce2(a0, a1);
        if ((lane & 1) == 0) s_r1[(c0_is_e ? HALF_ : 0) + row] = r1;
    }
    __syncthreads();

    if (tid < 2 * HALF_) s_r1[tid] += s_r2[tid];
    __syncthreads();

    // out = (r @ Wrp + brp) @ Wout + bout
    if (tid < H_) {
        float acc = brp[tid];
        #pragma unroll 16
        for (int k = 0; k < 2 * HALF_; ++k) acc = fmaf(s_r1[k], Wrp[k * H_ + tid], acc);
        s_tmp[tid] = acc;
    }
    __syncthreads();
    if (tid < V_) {
        float acc = bout[tid];
        #pragma unroll 16
        for (int d = 0; d < H_; ++d) acc = fmaf(s_tmp[d], Wout[d * V_ + tid], acc);
        out[b * V_ + tid] = acc;
    }
}

// ---------------------------------------------------------------------------
extern "C" void kernel_launch(void* const* d_in, const int* in_sizes, int n_in,
                              void* d_out, int out_size)
{
    const int*   seq   = (const int*)d_in[0];
    const float* embed = (const float*)d_in[1];
    const float* W1    = (const float*)d_in[2];
    const float* b1    = (const float*)d_in[3];
    const float* W2    = (const float*)d_in[4];
    const float* b2    = (const float*)d_in[5];
    const float* gamma = (const float*)d_in[6];
    const float* beta  = (const float*)d_in[7];
    const float* Ws    = (const float*)d_in[8];
    const float* bs    = (const float*)d_in[9];
    const float* We    = (const float*)d_in[10];
    const float* be    = (const float*)d_in[11];
    const float* Wrp   = (const float*)d_in[12];
    const float* brp   = (const float*)d_in[13];
    const float* Wout  = (const float*)d_in[14];
    const float* bout  = (const float*)d_in[15];
    float* out = (float*)d_out;

    static int smem_set = 0;
    const int smem_bytes = (16384 + L_PAD + 256) * 4 + 256;
    if (!smem_set) {
        cudaFuncSetAttribute(scan_kernel,
                             cudaFuncAttributeMaxDynamicSharedMemorySize, smem_bytes);
        smem_set = 1;
    }

    build_tables<<<V_, 128>>>(embed, W1, b1, W2, b2, gamma, beta, Ws, bs, We, be);
    scan_kernel<<<B_, NT_, smem_bytes>>>(seq, Wrp, brp, Wout, bout, out);
}